// round 16
// baseline (speedup 1.0000x reference)
#include <cuda_runtime.h>
#include <cuda_bf16.h>
#include <cstdint>

// Problem shape (fixed by dataset: X is [8192, 64] fp32)
#define NROWS 8192
#define DDIM  64

// -------- device scratch (static allocation only) ---------------------------
__device__ float g_sq[NROWS];         // per-row ||x||^2 (fp32, exact)
__device__ float g_cp[256 * DDIM];    // partial column sums (256 blocks x 64)
__device__ float g_invl;              // log2(e) / (2*sigma^2)

// ---------- kernel 1 (fused): per-row ||x||^2 + partial column sums ---------
__global__ void gk_pre(const float* __restrict__ X) {
    __shared__ float scs[256];
    int t = threadIdx.x;
    {
        int row = blockIdx.x * 32 + (t >> 3);
        int sub = t & 7;
        const float4* p = reinterpret_cast<const float4*>(X + (size_t)row * DDIM + sub * 8);
        float4 a = p[0], b = p[1];
        float s = a.x * a.x + a.y * a.y + a.z * a.z + a.w * a.w
                + b.x * b.x + b.y * b.y + b.z * b.z + b.w * b.w;
        s += __shfl_xor_sync(0xffffffffu, s, 1);
        s += __shfl_xor_sync(0xffffffffu, s, 2);
        s += __shfl_xor_sync(0xffffffffu, s, 4);
        if (sub == 0) g_sq[row] = s;
    }
    {
        int col = t & 63, stripe = t >> 6;     // 4 stripes x 8 rows
        int base = blockIdx.x * 32 + stripe * 8;
        float s = 0.f;
        #pragma unroll
        for (int r = 0; r < 8; r++)
            s += X[(size_t)(base + r) * DDIM + col];
        scs[t] = s;
        __syncthreads();
        if (t < 64) {
            float c = 0.f;
            #pragma unroll
            for (int st = 0; st < 4; st++) c += scs[st * 64 + t];
            g_cp[blockIdx.x * 64 + t] = c;
        }
    }
}

// --------------- kernel 2: finish stats -> log2e/(2 sigma^2) ----------------
// mean(d2) = 2*mean(sq) - 2*||mu||^2 (clamp correction is O(1e-9) relative)
__global__ void gk_finish(int n) {
    __shared__ float ssq[1024];
    __shared__ float smu[64];
    int t = threadIdx.x;
    float q = 0.f;
    for (int r = t; r < n; r += 1024) q += g_sq[r];
    ssq[t] = q;
    __syncthreads();
    for (int sft = 512; sft > 0; sft >>= 1) {
        if (t < sft) ssq[t] += ssq[t + sft];
        __syncthreads();
    }
    if (t < 64) {
        float c = 0.f;
        #pragma unroll
        for (int b = 0; b < 256; b++) c += g_cp[b * 64 + t];
        smu[t] = c / (float)n;                 // mu_k
    }
    __syncthreads();
    if (t == 0) {
        float mu2 = 0.f;
        #pragma unroll
        for (int k = 0; k < 64; k++) mu2 += smu[k] * smu[k];
        float meansq = ssq[0] / (float)n;
        float meand2 = 2.f * meansq - 2.f * mu2;   // ALPHA = 1
        g_invl = 1.44269504f / (2.f * meand2);     // log2(e)/(2 sigma^2)
    }
}

// ------------------------- kernel 3: main tile kernel ------------------------
// Tile = 128(m) x 64(n), 256 threads, 8 warps as 4(m) x 2(n), warp tile 32x32.
// acc = 32 floats/thread -> ~70 regs -> 3 CTAs/SM (37.5% occ).
// Triangular cover on (128-row, 64-col) blocks: keep bj2 >= 2*bi.
// Diagonal-adjacent tiles double-write a 64x64 block with bitwise-identical
// values (deterministic). Mirror = direct register scatter (R13 proven).
#define BM 128
#define BN 64
#define SBH 72          // bf16 per row in operand tiles (144 bytes)

#define NBI 64          // row blocks of 128
#define NBJ 128         // col blocks of 64
#define NTRI2 4160      // sum_{bi} (128 - 2*bi) = 64*65

static constexpr int OFF_BS  = BM * SBH * 2;          // 18432 (A tile)
static constexpr int OFF_SQI = OFF_BS + BN * SBH * 2; // +9216 = 27648
static constexpr int OFF_SQJ = OFF_SQI + 512;         // 28160
static constexpr int SMEM_BYTES = OFF_SQJ + 256;      // 28416

__device__ __forceinline__ void mma_bf16(float* c, const uint32_t* a, const uint32_t* b) {
    asm volatile(
        "mma.sync.aligned.m16n8k16.row.col.f32.bf16.bf16.f32 "
        "{%0,%1,%2,%3}, {%4,%5,%6,%7}, {%8,%9}, {%0,%1,%2,%3};"
        : "+f"(c[0]), "+f"(c[1]), "+f"(c[2]), "+f"(c[3])
        : "r"(a[0]), "r"(a[1]), "r"(a[2]), "r"(a[3]), "r"(b[0]), "r"(b[1]));
}

__device__ __forceinline__ float gauss_elem(float acc, float sj, float nsqi, float invl) {
    float u = fmaf(2.f, acc, nsqi - sj);   // u = 2*dot - sq_i - sq_j = -d2
    float a = fminf(u * invl, 0.f);        // = -max(d2,0)*log2e/(2 sigma^2)
    float r;
    asm("ex2.approx.f32 %0, %1;" : "=f"(r) : "f"(a));
    return r;
}

// Start index of triangle row bi: S(bi) = bi*(129-bi)
__device__ __forceinline__ int tri2_start(int bi) {
    return bi * (2 * NBJ + 2 - 2 * bi + 2 * bi - (NBJ + 2 - 129)) ;
}

__device__ __forceinline__ uint32_t pack_bf16x2(float lo, float hi) {
    __nv_bfloat162 h = __floats2bfloat162_rn(lo, hi);   // x=lo (low half), y=hi
    return *reinterpret_cast<uint32_t*>(&h);
}

__global__ void __launch_bounds__(256, 3)
gk_main(const float* __restrict__ X, float* __restrict__ out, int n) {
    extern __shared__ unsigned char smem[];
    unsigned char* Asb = smem;                 // bf16 [128][72]
    unsigned char* Bsb = smem + OFF_BS;        // bf16 [64][72]
    float* sqi = reinterpret_cast<float*>(smem + OFF_SQI);   // [128]
    float* sqj = reinterpret_cast<float*>(smem + OFF_SQJ);   // [64]

    int tid = threadIdx.x;

    // ---- decode triangular block index: S(bi) = bi*(129-bi) <= t -----------
    int t = blockIdx.x;
    int bi = (int)((129.0f - sqrtf(16641.0f - 4.0f * (float)t)) * 0.5f);
    if (bi < 0) bi = 0;
    if (bi > NBI - 1) bi = NBI - 1;
    while (bi + 1 <= NBI - 1 && (bi + 1) * (129 - (bi + 1)) <= t) bi++;
    while (bi * (129 - bi) > t) bi--;
    int bj2 = 2 * bi + (t - bi * (129 - bi));   // 2*bi .. 127

    float invl = g_invl;   // hoisted

    // ---- cooperative load: fp32 -> bf16 tiles (conflict-free STS.128) ------
    {
        const float* gA = X + (size_t)bi * BM * DDIM;
        const float* gB = X + (size_t)bj2 * BN * DDIM;
        #pragma unroll
        for (int it = 0; it < 4; it++) {       // A: 1024 16B-units
            int e = tid + 256 * it;
            int row = e >> 3, u = e & 7;
            const float4* pa = reinterpret_cast<const float4*>(gA + row * DDIM + u * 8);
            float4 a0 = pa[0], a1 = pa[1];
            uint4 wa;
            wa.x = pack_bf16x2(a0.x, a0.y); wa.y = pack_bf16x2(a0.z, a0.w);
            wa.z = pack_bf16x2(a1.x, a1.y); wa.w = pack_bf16x2(a1.z, a1.w);
            *reinterpret_cast<uint4*>(Asb + row * (SBH * 2) + u * 16) = wa;
        }
        #pragma unroll
        for (int it = 0; it < 2; it++) {       // B: 512 16B-units
            int e = tid + 256 * it;
            int row = e >> 3, u = e & 7;
            const float4* pb = reinterpret_cast<const float4*>(gB + row * DDIM + u * 8);
            float4 b0 = pb[0], b1 = pb[1];
            uint4 wb;
            wb.x = pack_bf16x2(b0.x, b0.y); wb.y = pack_bf16x2(b0.z, b0.w);
            wb.z = pack_bf16x2(b1.x, b1.y); wb.w = pack_bf16x2(b1.z, b1.w);
            *reinterpret_cast<uint4*>(Bsb + row * (SBH * 2) + u * 16) = wb;
        }
        if (tid < 128)      sqi[tid] = g_sq[bi * BM + tid];
        else if (tid < 192) sqj[tid - 128] = g_sq[bj2 * BN + (tid - 128)];
    }
    __syncthreads();

    // ---- warp-level bf16 GEMM (m16n8k16), warp tile 32x32, 4(m)x2(n) ------
    int wid = tid >> 5, lane = tid & 31;
    int wm = wid & 3, wn = wid >> 2;
    int gq = lane >> 2, q4 = lane & 3;

    float acc[2][4][4];
    #pragma unroll
    for (int mt = 0; mt < 2; mt++)
        #pragma unroll
        for (int nt = 0; nt < 4; nt++)
            #pragma unroll
            for (int r = 0; r < 4; r++) acc[mt][nt][r] = 0.f;

    #pragma unroll
    for (int kc = 0; kc < 4; kc++) {
        int kb = kc * 32 + q4 * 4;             // byte offset within k-chunk
        uint32_t afr[2][4];
        #pragma unroll
        for (int mt = 0; mt < 2; mt++) {
            int row = wm * 32 + mt * 16 + gq;
            const unsigned char* base0 = Asb + row * (SBH * 2) + kb;
            const unsigned char* base1 = Asb + (row + 8) * (SBH * 2) + kb;
            afr[mt][0] = *reinterpret_cast<const uint32_t*>(base0);
            afr[mt][1] = *reinterpret_cast<const uint32_t*>(base1);
            afr[mt][2] = *reinterpret_cast<const uint32_t*>(base0 + 16);
            afr[mt][3] = *reinterpret_cast<const uint32_t*>(base1 + 16);
        }
        uint32_t bfr[4][2];
        #pragma unroll
        for (int nt = 0; nt < 4; nt++) {
            int col = wn * 32 + nt * 8 + gq;
            const unsigned char* base = Bsb + col * (SBH * 2) + kb;
            bfr[nt][0] = *reinterpret_cast<const uint32_t*>(base);
            bfr[nt][1] = *reinterpret_cast<const uint32_t*>(base + 16);
        }
        #pragma unroll
        for (int mt = 0; mt < 2; mt++)
            #pragma unroll
            for (int nt = 0; nt < 4; nt++)
                mma_bf16(acc[mt][nt], afr[mt], bfr[nt]);
    }

    // ---- epilogue: transform acc in place, direct STG of primary tile ------
    #pragma unroll
    for (int mt = 0; mt < 2; mt++) {
        #pragma unroll
        for (int rr = 0; rr < 2; rr++) {
            int rloc = wm * 32 + mt * 16 + gq + rr * 8;
            int grow = bi * BM + rloc;
            float nsqi = -sqi[rloc];
            float* orow = out + (size_t)grow * n + bj2 * BN;
            #pragma unroll
            for (int nt = 0; nt < 4; nt++) {
                int c0 = wn * 32 + nt * 8 + 2 * q4;
                float2 v;
                v.x = gauss_elem(acc[mt][nt][rr * 2 + 0], sqj[c0],     nsqi, invl);
                v.y = gauss_elem(acc[mt][nt][rr * 2 + 1], sqj[c0 + 1], nsqi, invl);
                acc[mt][nt][rr * 2 + 0] = v.x;     // keep for mirror
                acc[mt][nt][rr * 2 + 1] = v.y;
                *reinterpret_cast<float2*>(orow + c0) = v;
            }
        }
    }

    // ---- mirror tile: direct register scatter (no staging, no barriers) ----
    // Diagonal-adjacent tiles re-write a 64x64 block with identical values.
    {
        float* obase = out + (size_t)bj2 * BN * n + bi * BM;
        #pragma unroll
        for (int mt = 0; mt < 2; mt++) {
            #pragma unroll
            for (int rr = 0; rr < 2; rr++) {
                int rloc = wm * 32 + mt * 16 + gq + rr * 8;
                #pragma unroll
                for (int nt = 0; nt < 4; nt++) {
                    int c0 = wn * 32 + nt * 8 + 2 * q4;
                    obase[(size_t)c0 * n + rloc]       = acc[mt][nt][rr * 2 + 0];
                    obase[(size_t)(c0 + 1) * n + rloc] = acc[mt][nt][rr * 2 + 1];
                }
            }
        }
    }
}

// ------------------------------ launch ---------------------------------------
extern "C" void kernel_launch(void* const* d_in, const int* in_sizes, int n_in,
                              void* d_out, int out_size) {
    const float* X = (const float*)d_in[0];
    int n = in_sizes[0] / DDIM;          // 8192
    float* out = (float*)d_out;

    cudaFuncSetAttribute(gk_main, cudaFuncAttributeMaxDynamicSharedMemorySize,
                         SMEM_BYTES);

    gk_pre<<<256, 256>>>(X);
    gk_finish<<<1, 1024>>>(n);
    gk_main<<<NTRI2, 256, SMEM_BYTES>>>(X, out, n);
}

// round 17
// speedup vs baseline: 1.0617x; 1.0617x over previous
#include <cuda_runtime.h>
#include <cuda_bf16.h>
#include <cstdint>

// Problem shape (fixed by dataset: X is [8192, 64] fp32)
#define NROWS 8192
#define DDIM  64

// -------- device scratch (static allocation only) ---------------------------
__device__ float g_sq[NROWS];         // per-row ||x||^2 (fp32, exact)
__device__ float g_cp[512 * DDIM];    // partial column sums (512 blocks x 64)
__device__ float g_invl;              // log2(e) / (2*sigma^2)

// ---------- kernel 1 (fused): per-row ||x||^2 + partial column sums ---------
// 512 blocks x 256 threads; block handles 16 rows (4 KB chunk).
__global__ void gk_pre(const float* __restrict__ X) {
    __shared__ float scs[256];
    int t = threadIdx.x;

    // Phase A: row squared norms. 16 threads per row, 1 float4 each.
    {
        int row = blockIdx.x * 16 + (t >> 4);
        int sub = t & 15;
        float4 a = reinterpret_cast<const float4*>(X + (size_t)row * DDIM)[sub];
        float s = a.x * a.x + a.y * a.y + a.z * a.z + a.w * a.w;
        s += __shfl_xor_sync(0xffffffffu, s, 1);
        s += __shfl_xor_sync(0xffffffffu, s, 2);
        s += __shfl_xor_sync(0xffffffffu, s, 4);
        s += __shfl_xor_sync(0xffffffffu, s, 8);
        if (sub == 0) g_sq[row] = s;
    }

    // Phase B: partial column sums for the mean vector.
    {
        int col = t & 63, stripe = t >> 6;     // 4 stripes x 4 rows
        int base = blockIdx.x * 16 + stripe * 4;
        float s = 0.f;
        #pragma unroll
        for (int r = 0; r < 4; r++)
            s += X[(size_t)(base + r) * DDIM + col];
        scs[t] = s;
        __syncthreads();
        if (t < 64) {
            float c = 0.f;
            #pragma unroll
            for (int st = 0; st < 4; st++) c += scs[st * 64 + t];
            g_cp[blockIdx.x * 64 + t] = c;
        }
    }
}

// --------------- kernel 2: finish stats -> log2e/(2 sigma^2) ----------------
// mean(d2) = 2*mean(sq) - 2*||mu||^2 (clamp correction is O(1e-9) relative)
__global__ void gk_finish(int n) {
    __shared__ float ssq[1024];
    __shared__ float smu[64];
    int t = threadIdx.x;
    float q = 0.f;
    for (int r = t; r < n; r += 1024) q += g_sq[r];
    ssq[t] = q;
    __syncthreads();
    for (int sft = 512; sft > 0; sft >>= 1) {
        if (t < sft) ssq[t] += ssq[t + sft];
        __syncthreads();
    }
    if (t < 64) {
        float c = 0.f;
        #pragma unroll
        for (int b = 0; b < 512; b++) c += g_cp[b * 64 + t];
        smu[t] = c / (float)n;                 // mu_k
    }
    __syncthreads();
    if (t == 0) {
        float mu2 = 0.f;
        #pragma unroll
        for (int k = 0; k < 64; k++) mu2 += smu[k] * smu[k];
        float meansq = ssq[0] / (float)n;
        float meand2 = 2.f * meansq - 2.f * mu2;   // ALPHA = 1
        g_invl = 1.44269504f / (2.f * meand2);     // log2(e)/(2 sigma^2)
    }
}

// ------------------------- kernel 3: main tile kernel ------------------------
// Triangular grid (bi <= bj); 128x128 tile; bf16 mma.sync.m16n8k16.
// Fragments via ldmatrix.x4 (LDSM) — 6 inst per k-chunk instead of 24 LDS.32.
// Primary: direct STG.64. Mirror: direct register STG.32 scatter (R14 proven).
#define BM 128
#define BN 128
#define SBH 72          // bf16 per row in operand tiles (144 bytes)

#define NTILE 64        // 8192 / 128
#define NTRI  (NTILE * (NTILE + 1) / 2)   // 2080

static constexpr int OFF_BS  = BM * SBH * 2;          // 18432
static constexpr int OFF_SQI = 2 * BM * SBH * 2;      // 36864
static constexpr int OFF_SQJ = OFF_SQI + 512;
static constexpr int SMEM_BYTES = OFF_SQJ + 512;      // 37888

__device__ __forceinline__ uint32_t smem_u32(const void* p) {
    uint32_t a;
    asm("{ .reg .u64 t; cvta.to.shared.u64 t, %1; cvt.u32.u64 %0, t; }"
        : "=r"(a) : "l"(p));
    return a;
}

#define LDSM_X4(r0, r1, r2, r3, addr) \
    asm volatile("ldmatrix.sync.aligned.m8n8.x4.shared.b16 {%0,%1,%2,%3}, [%4];" \
        : "=r"(r0), "=r"(r1), "=r"(r2), "=r"(r3) : "r"(addr))

__device__ __forceinline__ void mma_bf16(float* c, const uint32_t* a, const uint32_t* b) {
    asm volatile(
        "mma.sync.aligned.m16n8k16.row.col.f32.bf16.bf16.f32 "
        "{%0,%1,%2,%3}, {%4,%5,%6,%7}, {%8,%9}, {%0,%1,%2,%3};"
        : "+f"(c[0]), "+f"(c[1]), "+f"(c[2]), "+f"(c[3])
        : "r"(a[0]), "r"(a[1]), "r"(a[2]), "r"(a[3]), "r"(b[0]), "r"(b[1]));
}

__device__ __forceinline__ float gauss_elem(float acc, float sj, float nsqi, float invl) {
    float u = fmaf(2.f, acc, nsqi - sj);   // u = 2*dot - sq_i - sq_j = -d2
    float a = fminf(u * invl, 0.f);        // = -max(d2,0)*log2e/(2 sigma^2)
    float r;
    asm("ex2.approx.f32 %0, %1;" : "=f"(r) : "f"(a));
    return r;
}

// Start index of triangle row bi: Start(bi) = bi*(2*NTILE+1-bi)/2
__device__ __forceinline__ int tri_start(int bi) {
    return (bi * (2 * NTILE + 1 - bi)) >> 1;
}

__device__ __forceinline__ uint32_t pack_bf16x2(float lo, float hi) {
    __nv_bfloat162 h = __floats2bfloat162_rn(lo, hi);   // x=lo (low half), y=hi
    return *reinterpret_cast<uint32_t*>(&h);
}

__global__ void __launch_bounds__(256, 2)
gk_main(const float* __restrict__ X, float* __restrict__ out, int n) {
    extern __shared__ unsigned char smem[];
    unsigned char* Asb = smem;                 // bf16 [128][72]
    unsigned char* Bsb = smem + OFF_BS;        // bf16 [128][72]
    float* sqi = reinterpret_cast<float*>(smem + OFF_SQI);   // [128]
    float* sqj = reinterpret_cast<float*>(smem + OFF_SQJ);   // [128]

    int tid = threadIdx.x;

    // ---- decode triangular block index: bi <= bj ---------------------------
    int t = blockIdx.x;
    int bi = (int)((129.0f - sqrtf(16641.0f - 8.0f * (float)t)) * 0.5f);
    if (bi < 0) bi = 0;
    if (bi > NTILE - 1) bi = NTILE - 1;
    while (bi + 1 <= NTILE - 1 && tri_start(bi + 1) <= t) bi++;
    while (tri_start(bi) > t) bi--;
    int bj = bi + (t - tri_start(bi));

    float invl = g_invl;   // hoisted: latency hides under tile load + GEMM

    // ---- cooperative load: fp32 -> bf16 tiles (conflict-free STS.128) ------
    {
        const float* gA = X + (size_t)bi * BM * DDIM;
        const float* gB = X + (size_t)bj * BN * DDIM;
        #pragma unroll
        for (int it = 0; it < 4; it++) {
            int e = tid + 256 * it;
            int row = e >> 3, u = e & 7;
            const float4* pa = reinterpret_cast<const float4*>(gA + row * DDIM + u * 8);
            const float4* pb = reinterpret_cast<const float4*>(gB + row * DDIM + u * 8);
            float4 a0 = pa[0], a1 = pa[1];
            float4 b0 = pb[0], b1 = pb[1];
            uint4 wa, wb;
            wa.x = pack_bf16x2(a0.x, a0.y); wa.y = pack_bf16x2(a0.z, a0.w);
            wa.z = pack_bf16x2(a1.x, a1.y); wa.w = pack_bf16x2(a1.z, a1.w);
            wb.x = pack_bf16x2(b0.x, b0.y); wb.y = pack_bf16x2(b0.z, b0.w);
            wb.z = pack_bf16x2(b1.x, b1.y); wb.w = pack_bf16x2(b1.z, b1.w);
            int off = row * (SBH * 2) + u * 16;
            *reinterpret_cast<uint4*>(Asb + off) = wa;
            *reinterpret_cast<uint4*>(Bsb + off) = wb;
        }
        if (tid < 128) sqi[tid] = g_sq[bi * BM + tid];
        else           sqj[tid - 128] = g_sq[bj * BN + (tid - 128)];
    }
    __syncthreads();

    // ---- warp-level bf16 GEMM via ldmatrix, warp tile 32x64, 4(m)x2(n) ----
    int wid = tid >> 5, lane = tid & 31;
    int wm = wid & 3, wn = wid >> 2;
    int gq = lane >> 2, q4 = lane & 3;

    // LDSM lane roles:
    //  A mats per (kc,mt): (r0-7,k0),(r8-15,k0),(r0-7,k8),(r8-15,k8)
    //  B mats per (kc,p):  (c0-7,k0),(c0-7,k8),(c8-15,k0),(c8-15,k8)
    uint32_t aBase, bBase;
    {
        int aRow = wm * 32 + (lane & 7) + ((lane >> 3) & 1) * 8;
        int aCol = (lane >> 4) * 16;
        aBase = smem_u32(Asb) + aRow * (SBH * 2) + aCol;
        int bCol = wn * 64 + (lane & 7) + ((lane >> 4) & 1) * 8;
        int bOff = ((lane >> 3) & 1) * 16;
        bBase = smem_u32(Bsb) + bCol * (SBH * 2) + bOff;
    }

    float acc[2][8][4];
    #pragma unroll
    for (int mt = 0; mt < 2; mt++)
        #pragma unroll
        for (int nt = 0; nt < 8; nt++)
            #pragma unroll
            for (int r = 0; r < 4; r++) acc[mt][nt][r] = 0.f;

    #pragma unroll
    for (int kc = 0; kc < 4; kc++) {
        uint32_t afr[2][4];
        #pragma unroll
        for (int mt = 0; mt < 2; mt++) {
            uint32_t addr = aBase + mt * 16 * (SBH * 2) + kc * 32;
            LDSM_X4(afr[mt][0], afr[mt][1], afr[mt][2], afr[mt][3], addr);
        }
        uint32_t bfr[8][2];
        #pragma unroll
        for (int p = 0; p < 4; p++) {
            uint32_t addr = bBase + p * 16 * (SBH * 2) + kc * 32;
            LDSM_X4(bfr[2 * p][0], bfr[2 * p][1], bfr[2 * p + 1][0], bfr[2 * p + 1][1], addr);
        }
        #pragma unroll
        for (int mt = 0; mt < 2; mt++)
            #pragma unroll
            for (int nt = 0; nt < 8; nt++)
                mma_bf16(acc[mt][nt], afr[mt], bfr[nt]);
    }

    // ---- epilogue: transform acc in place, direct STG of primary tile ------
    #pragma unroll
    for (int mt = 0; mt < 2; mt++) {
        #pragma unroll
        for (int rr = 0; rr < 2; rr++) {
            int rloc = wm * 32 + mt * 16 + gq + rr * 8;
            int grow = bi * BM + rloc;
            float nsqi = -sqi[rloc];
            float* orow = out + (size_t)grow * n + bj * BN;
            #pragma unroll
            for (int nt = 0; nt < 8; nt++) {
                int c0 = wn * 64 + nt * 8 + 2 * q4;
                float2 v;
                v.x = gauss_elem(acc[mt][nt][rr * 2 + 0], sqj[c0],     nsqi, invl);
                v.y = gauss_elem(acc[mt][nt][rr * 2 + 1], sqj[c0 + 1], nsqi, invl);
                acc[mt][nt][rr * 2 + 0] = v.x;     // keep for mirror
                acc[mt][nt][rr * 2 + 1] = v.y;
                *reinterpret_cast<float2*>(orow + c0) = v;
            }
        }
    }

    // ---- mirror tile: direct register scatter (no staging, no barriers) ----
    if (bi != bj) {
        float* obase = out + (size_t)bj * BN * n + bi * BM;
        #pragma unroll
        for (int mt = 0; mt < 2; mt++) {
            #pragma unroll
            for (int rr = 0; rr < 2; rr++) {
                int rloc = wm * 32 + mt * 16 + gq + rr * 8;
                #pragma unroll
                for (int nt = 0; nt < 8; nt++) {
                    int c0 = wn * 64 + nt * 8 + 2 * q4;
                    obase[(size_t)c0 * n + rloc]       = acc[mt][nt][rr * 2 + 0];
                    obase[(size_t)(c0 + 1) * n + rloc] = acc[mt][nt][rr * 2 + 1];
                }
            }
        }
    }
}

// ------------------------------ launch ---------------------------------------
extern "C" void kernel_launch(void* const* d_in, const int* in_sizes, int n_in,
                              void* d_out, int out_size) {
    const float* X = (const float*)d_in[0];
    int n = in_sizes[0] / DDIM;          // 8192
    float* out = (float*)d_out;

    cudaFuncSetAttribute(gk_main, cudaFuncAttributeMaxDynamicSharedMemorySize,
                         SMEM_BYTES);

    gk_pre<<<512, 256>>>(X);
    gk_finish<<<1, 1024>>>(n);
    gk_main<<<NTRI, 256, SMEM_BYTES>>>(X, out, n);
}